// round 8
// baseline (speedup 1.0000x reference)
#include <cuda_runtime.h>
#include <cuda_fp16.h>
#include <mma.h>
using namespace nvcuda;

#define NN 50000          // nodes per type
#define NE 1600000        // edges per edge type
#define CIN 11
#define HD 64
#define CAP 128           // max in-degree bucket (Poisson(32): P(>=128) ~ e^-81)
#define N16 (NN*16)
#define N64 (NN*64)

// ---------------- scratch (device globals; no allocation) ----------------
__device__ int            g_cnt[4][NN];       // per-edge-type in-degree
__device__ unsigned short g_col[4][NN*CAP];   // bucketed source ids (ushort)
__device__ __half g_x16[2][N16];        // fp16 x padded to 16-half rows
__device__ __half g_h1s16[N64], g_h1p16[N64];    // layer-1 activations (fp16)
__device__ __half g_wb1[2][48*64];      // fp16 layer-1 weights: 3 segs x 16 x 64
__device__ __half g_wb2[2][192*64];     // fp16 layer-2 weights: 3 segs x 64 x 64
__device__ float  g_b1[2][HD], g_b2[2][HD];   // bias pair sums

// ---------------- fused setup ----------------
#define R0 (4*NN)          // zero cnt
#define R1 (2*N16)         // xpad
#define R2 (2*48*64)       // wb1
#define R3 (2*192*64)      // wb2
#define R4 (2*2*HD)        // bias pairs
#define RTOT (R0+R1+R2+R3+R4)
__global__ void setup_kernel(const float* __restrict__ xs, const float* __restrict__ xp,
                             const float* __restrict__ w1l, const float* __restrict__ w1r,
                             const float* __restrict__ w2l, const float* __restrict__ w2r,
                             const float* __restrict__ b1l, const float* __restrict__ b2l) {
    int i = blockIdx.x*blockDim.x + threadIdx.x;
    if (i < R0) { ((int*)g_cnt)[i] = 0; return; }
    i -= R0;
    if (i < R1) {
        int half_ = i / N16;
        int j = i - half_*N16;
        int node = j >> 4, c = j & 15;
        const float* x = half_ ? xp : xs;
        ((__half*)g_x16)[i] = (c < CIN) ? __float2half_rn(x[node*CIN + c]) : __half(0.f);
        return;
    }
    i -= R1;
    if (i < R2) {
        int ty = i / 3072;
        int j = i - ty*3072;
        int r = j >> 6, c = j & 63;
        int seg = r >> 4, k = r & 15;
        float v = 0.f;
        if (k < CIN) {
            if (seg < 2) v = w1l[(seg*2 + ty)*CIN*HD + k*HD + c];
            else         v = w1r[ty*CIN*HD + k*HD + c] + w1r[(2+ty)*CIN*HD + k*HD + c];
        }
        g_wb1[ty][r*64 + c] = __float2half_rn(v);
        return;
    }
    i -= R2;
    if (i < R3) {
        int ty = i / 12288;
        int j = i - ty*12288;
        int r = j >> 6, c = j & 63;
        int seg = r >> 6, k = r & 63;
        float v;
        if (seg < 2) v = w2l[(seg*2 + ty)*HD*HD + k*HD + c];
        else         v = w2r[ty*HD*HD + k*HD + c] + w2r[(2+ty)*HD*HD + k*HD + c];
        g_wb2[ty][r*64 + c] = __float2half_rn(v);
        return;
    }
    i -= R3;
    if (i < R4) {
        int which = i >> 7;
        int ty = (i >> 6) & 1;
        int c = i & 63;
        if (which == 0) g_b1[ty][c] = b1l[ty*HD + c] + b1l[(2+ty)*HD + c];
        else            g_b2[ty][c] = b2l[ty*HD + c] + b2l[(2+ty)*HD + c];
    }
}

// ---------------- single-pass bucket placement (4 edges/thread) ------------
#define NE4 (NE/4)
#define EBLK4 ((NE4 + 255) / 256)
__global__ void place_all_kernel(const int* __restrict__ e0, const int* __restrict__ e1,
                                 const int* __restrict__ e2, const int* __restrict__ e3) {
    int t = blockIdx.x / EBLK4;
    int p = (blockIdx.x - t*EBLK4)*blockDim.x + threadIdx.x;
    if (p >= NE4) return;
    const int* ei = (t==0) ? e0 : (t==1) ? e1 : (t==2) ? e2 : e3;
    int4 s4 = *(const int4*)(ei + 4*p);
    int4 d4 = *(const int4*)(ei + NE + 4*p);
    int* cnt = g_cnt[t];
    unsigned short* col = g_col[t];
    int pos;
    pos = atomicAdd(&cnt[d4.x], 1); if (pos < CAP) col[(long)d4.x*CAP + pos] = (unsigned short)s4.x;
    pos = atomicAdd(&cnt[d4.y], 1); if (pos < CAP) col[(long)d4.y*CAP + pos] = (unsigned short)s4.y;
    pos = atomicAdd(&cnt[d4.z], 1); if (pos < CAP) col[(long)d4.z*CAP + pos] = (unsigned short)s4.z;
    pos = atomicAdd(&cnt[d4.w], 1); if (pos < CAP) col[(long)d4.w*CAP + pos] = (unsigned short)s4.w;
}

// ---------------- fused gather + wmma GEMM ----------------------------------
// Block = 64 destination nodes of node-type ty (grid.y).
// seg0: mean over edge type ty    (sources = srcS, shop-sourced)
// seg1: mean over edge type ty+2  (sources = srcP, public-sourced)
// seg2: node's own features (A2[ty], direct load)
// C = relu(sum_seg Aseg@Bseg + bias); final_: fused 64->1 linear into out.
struct FArgs {
    const __half *srcS, *srcP;
    const __half *A2[2];
    const __half *B[2];
    const float  *bias[2];
    __half *C16[2];
    const float *wlin[2], *bfin[2];
    float *out[2];
    int final_;
};

#define ASTR 72
#define BSTR 72
#define CSTR 68

template<int LDA>
__global__ void fgemm_kernel(FArgs g) {
    __shared__ char smem[64*ASTR*2 + 64*BSTR*2];   // 18432 B
    __half* As = (__half*)smem;
    __half* Bs = (__half*)(smem + 64*ASTR*2);
    float*  Cs = (float*)smem;                      // aliased after compute

    const int tid = threadIdx.x;
    const int ty  = blockIdx.y;
    const int m0  = blockIdx.x*64;
    const __half* B = g.B[ty];

    wmma::fragment<wmma::matrix_a, 16,16,16, __half, wmma::row_major> af;
    wmma::fragment<wmma::matrix_b, 16,16,16, __half, wmma::row_major> bf0, bf1;
    wmma::fragment<wmma::accumulator, 16,16,16, float> c0, c1;
    wmma::fill_fragment(c0, 0.f);
    wmma::fill_fragment(c1, 0.f);

    const int warp = tid >> 5;
    const int wr = warp >> 1;      // 0..3 : 16-row group
    const int wc = warp & 1;       // 0..1 : 32-col group
    const int r    = tid >> 2;     // node within tile
    const int lane = tid & 3;
    const int gm   = m0 + r;

#pragma unroll 1
    for (int seg = 0; seg < 3; seg++) {
        __syncthreads();
        if (seg < 2) {
            // ---- gather mean directly into As ----
            const int t = (seg == 0) ? ty : ty + 2;
            const __half* src = (seg == 0) ? g.srcS : g.srcP;
            int cnt = 0;
            if (gm < NN) cnt = g_cnt[t][gm];
            int deg = min(cnt, CAP);
            const unsigned short* col = g_col[t] + (long)gm*CAP;
            int e = 0, nd4 = deg & ~3;
            ushort4 nxt;
            if (nd4 > 0) nxt = *(const ushort4*)col;

            if (LDA == 64) {
                float acc[16];
#pragma unroll
                for (int j = 0; j < 16; j++) acc[j] = 0.f;
                for (; e < nd4; e += 4) {
                    ushort4 s = nxt;
                    if (e + 4 < nd4) nxt = *(const ushort4*)(col + e + 4);
                    const __half* p0 = src + (long)s.x*64 + lane*16;
                    const __half* p1 = src + (long)s.y*64 + lane*16;
                    const __half* p2 = src + (long)s.z*64 + lane*16;
                    const __half* p3 = src + (long)s.w*64 + lane*16;
                    float4 a0 = *(const float4*)p0;  float4 a1 = *(const float4*)(p0 + 8);
                    float4 b0 = *(const float4*)p1;  float4 b1 = *(const float4*)(p1 + 8);
                    float4 c0v = *(const float4*)p2; float4 c1v = *(const float4*)(p2 + 8);
                    float4 d0 = *(const float4*)p3;  float4 d1 = *(const float4*)(p3 + 8);
                    const __half2 *ha0=(const __half2*)&a0, *ha1=(const __half2*)&a1;
                    const __half2 *hb0=(const __half2*)&b0, *hb1=(const __half2*)&b1;
                    const __half2 *hc0=(const __half2*)&c0v,*hc1=(const __half2*)&c1v;
                    const __half2 *hd0=(const __half2*)&d0, *hd1=(const __half2*)&d1;
#pragma unroll
                    for (int j = 0; j < 4; j++) {
                        float2 f0 = __half22float2(ha0[j]);
                        float2 f1 = __half22float2(hb0[j]);
                        float2 f2 = __half22float2(hc0[j]);
                        float2 f3 = __half22float2(hd0[j]);
                        acc[2*j]   += (f0.x + f1.x) + (f2.x + f3.x);
                        acc[2*j+1] += (f0.y + f1.y) + (f2.y + f3.y);
                        float2 g0 = __half22float2(ha1[j]);
                        float2 g1 = __half22float2(hb1[j]);
                        float2 g2 = __half22float2(hc1[j]);
                        float2 g3 = __half22float2(hd1[j]);
                        acc[8+2*j]   += (g0.x + g1.x) + (g2.x + g3.x);
                        acc[8+2*j+1] += (g0.y + g1.y) + (g2.y + g3.y);
                    }
                }
                for (; e < deg; e++) {
                    int s0 = col[e];
                    const __half* p0 = src + (long)s0*64 + lane*16;
                    float4 a0 = *(const float4*)p0;
                    float4 a1 = *(const float4*)(p0 + 8);
                    const __half2 *ha0=(const __half2*)&a0, *ha1=(const __half2*)&a1;
#pragma unroll
                    for (int j = 0; j < 4; j++) {
                        float2 f0 = __half22float2(ha0[j]);
                        acc[2*j]   += f0.x;
                        acc[2*j+1] += f0.y;
                        float2 g0 = __half22float2(ha1[j]);
                        acc[8+2*j]   += g0.x;
                        acc[8+2*j+1] += g0.y;
                    }
                }
                float inv = 1.f / (float)max(cnt, 1);
                __half2 o[8];
#pragma unroll
                for (int j = 0; j < 8; j++)
                    o[j] = __floats2half2_rn(acc[2*j]*inv, acc[2*j+1]*inv);
                __half* dst = As + r*ASTR + lane*16;
                *(float4*)dst       = *(float4*)&o[0];
                *(float4*)(dst + 8) = *(float4*)&o[4];
            } else {
                // LDA == 16: 4 halves (8B) per lane
                float acc[4] = {0.f, 0.f, 0.f, 0.f};
                for (; e < nd4; e += 4) {
                    ushort4 s = nxt;
                    if (e + 4 < nd4) nxt = *(const ushort4*)(col + e + 4);
                    uint2 v0 = *(const uint2*)(src + (long)s.x*16 + lane*4);
                    uint2 v1 = *(const uint2*)(src + (long)s.y*16 + lane*4);
                    uint2 v2 = *(const uint2*)(src + (long)s.z*16 + lane*4);
                    uint2 v3 = *(const uint2*)(src + (long)s.w*16 + lane*4);
                    const __half2 *h0=(const __half2*)&v0, *h1=(const __half2*)&v1;
                    const __half2 *h2=(const __half2*)&v2, *h3=(const __half2*)&v3;
#pragma unroll
                    for (int j = 0; j < 2; j++) {
                        float2 f0 = __half22float2(h0[j]);
                        float2 f1 = __half22float2(h1[j]);
                        float2 f2 = __half22float2(h2[j]);
                        float2 f3 = __half22float2(h3[j]);
                        acc[2*j]   += (f0.x + f1.x) + (f2.x + f3.x);
                        acc[2*j+1] += (f0.y + f1.y) + (f2.y + f3.y);
                    }
                }
                for (; e < deg; e++) {
                    int s0 = col[e];
                    uint2 v0 = *(const uint2*)(src + (long)s0*16 + lane*4);
                    const __half2* h0 = (const __half2*)&v0;
#pragma unroll
                    for (int j = 0; j < 2; j++) {
                        float2 f0 = __half22float2(h0[j]);
                        acc[2*j]   += f0.x;
                        acc[2*j+1] += f0.y;
                    }
                }
                float inv = 1.f / (float)max(cnt, 1);
                __half2 o[2];
                o[0] = __floats2half2_rn(acc[0]*inv, acc[1]*inv);
                o[1] = __floats2half2_rn(acc[2]*inv, acc[3]*inv);
                *(float2*)(As + r*ASTR + lane*4) = *(float2*)o;
            }
        } else {
            // ---- direct self-features ----
            const __half* A = g.A2[ty];
            const int rowU = LDA >> 3;
            for (int u = tid; u < 64*rowU; u += 256) {
                int m = u / rowU;
                int h = (u - m*rowU) << 3;
                int gmm = m0 + m;
                float4 v = make_float4(0.f,0.f,0.f,0.f);
                if (gmm < NN) v = *(const float4*)(A + (long)gmm*LDA + h);
                *(float4*)(As + m*ASTR + h) = v;
            }
        }
        // ---- stage B segment ----
        for (int u = tid; u < LDA*8; u += 256) {
            int rr = u >> 3, c = (u & 7) << 3;
            *(float4*)(Bs + rr*BSTR + c) =
                *(const float4*)(B + (long)(seg*LDA + rr)*64 + c);
        }
        __syncthreads();
#pragma unroll
        for (int kc = 0; kc < (LDA >> 4); kc++) {
            wmma::load_matrix_sync(af, As + (wr*16)*ASTR + kc*16, ASTR);
            wmma::load_matrix_sync(bf0, Bs + (kc*16)*BSTR + wc*32, BSTR);
            wmma::load_matrix_sync(bf1, Bs + (kc*16)*BSTR + wc*32 + 16, BSTR);
            wmma::mma_sync(c0, af, bf0, c0);
            wmma::mma_sync(c1, af, bf1, c1);
        }
    }

    __syncthreads();
    wmma::store_matrix_sync(Cs + (wr*16)*CSTR + wc*32, c0, CSTR, wmma::mem_row_major);
    wmma::store_matrix_sync(Cs + (wr*16)*CSTR + wc*32 + 16, c1, CSTR, wmma::mem_row_major);
    __syncthreads();

    const float* bias = g.bias[ty];
    int cb = lane*16;
    if (g.final_) {
        const float* wl = g.wlin[ty];
        float s = 0.f;
#pragma unroll
        for (int c = 0; c < 16; c++) {
            float v = fmaxf(Cs[r*CSTR + cb + c] + bias[cb + c], 0.f);
            s = fmaf(v, wl[cb + c], s);
        }
        s += __shfl_xor_sync(0xffffffffu, s, 1, 4);
        s += __shfl_xor_sync(0xffffffffu, s, 2, 4);
        if (lane == 0 && gm < NN) g.out[ty][gm] = s + g.bfin[ty][0];
    } else if (gm < NN) {
        __half2 o[8];
#pragma unroll
        for (int j = 0; j < 8; j++) {
            float v0 = fmaxf(Cs[r*CSTR + cb + 2*j]   + bias[cb + 2*j],   0.f);
            float v1 = fmaxf(Cs[r*CSTR + cb + 2*j+1] + bias[cb + 2*j+1], 0.f);
            o[j] = __floats2half2_rn(v0, v1);
        }
        __half* dst = g.C16[ty] + (long)gm*HD + cb;
        *(float4*)dst       = *(float4*)&o[0];
        *(float4*)(dst + 8) = *(float4*)&o[4];
    }
}

// ---------------- launch ----------------
extern "C" void kernel_launch(void* const* d_in, const int* in_sizes, int n_in,
                              void* d_out, int out_size) {
    (void)in_sizes; (void)n_in; (void)out_size;
    const float* x_shop = (const float*)d_in[0];
    const float* x_pub  = (const float*)d_in[1];
    const float* w1_l   = (const float*)d_in[2];
    const float* b1_l   = (const float*)d_in[3];
    const float* w1_r   = (const float*)d_in[4];
    const float* w2_l   = (const float*)d_in[5];
    const float* b2_l   = (const float*)d_in[6];
    const float* w2_r   = (const float*)d_in[7];
    const float* wls    = (const float*)d_in[8];
    const float* bls    = (const float*)d_in[9];
    const float* wlp    = (const float*)d_in[10];
    const float* blp    = (const float*)d_in[11];
    const int* ei_ss    = (const int*)d_in[12];
    const int* ei_sp    = (const int*)d_in[13];
    const int* ei_ps    = (const int*)d_in[14];
    const int* ei_pp    = (const int*)d_in[15];

    __half *h1s16, *h1p16, *x16, *wb1, *wb2;
    float *b1, *b2;
    cudaGetSymbolAddress((void**)&h1s16, g_h1s16);
    cudaGetSymbolAddress((void**)&h1p16, g_h1p16);
    cudaGetSymbolAddress((void**)&x16,  g_x16);
    cudaGetSymbolAddress((void**)&wb1,  g_wb1);
    cudaGetSymbolAddress((void**)&wb2,  g_wb2);
    cudaGetSymbolAddress((void**)&b1,   g_b1);
    cudaGetSymbolAddress((void**)&b2,   g_b2);

    const int TB = 256;
    const int GB = (NN + 63) / 64;                // 782
    float* out = (float*)d_out;

    setup_kernel<<<(RTOT + TB - 1)/TB, TB>>>(x_shop, x_pub, w1_l, w1_r, w2_l, w2_r, b1_l, b2_l);
    place_all_kernel<<<4*EBLK4, TB>>>(ei_ss, ei_sp, ei_ps, ei_pp);

    // ---- layer 1: fused gather + GEMM -> fp16 h1 ----
    {
        FArgs a;
        a.srcS = x16;             a.srcP = x16 + (long)N16;
        a.A2[0] = x16;            a.A2[1] = x16 + (long)N16;
        a.B[0] = wb1;             a.B[1] = wb1 + 48*64;
        a.bias[0] = b1;           a.bias[1] = b1 + HD;
        a.C16[0] = h1s16;         a.C16[1] = h1p16;
        a.wlin[0] = a.wlin[1] = nullptr;
        a.bfin[0] = a.bfin[1] = nullptr;
        a.out[0] = a.out[1] = nullptr;
        a.final_ = 0;
        fgemm_kernel<16><<<dim3(GB,2), TB>>>(a);
    }

    // ---- layer 2: fused gather + GEMM + fused final linear ----
    {
        FArgs a;
        a.srcS = h1s16;           a.srcP = h1p16;
        a.A2[0] = h1s16;          a.A2[1] = h1p16;
        a.B[0] = wb2;             a.B[1] = wb2 + 192*64;
        a.bias[0] = b2;           a.bias[1] = b2 + HD;
        a.C16[0] = a.C16[1] = nullptr;
        a.wlin[0] = wls;          a.wlin[1] = wlp;
        a.bfin[0] = bls;          a.bfin[1] = blp;
        a.out[0] = out;           a.out[1] = out + NN;
        a.final_ = 1;
        fgemm_kernel<64><<<dim3(GB,2), TB>>>(a);
    }
}

// round 9
// speedup vs baseline: 1.1141x; 1.1141x over previous
#include <cuda_runtime.h>
#include <cuda_fp16.h>
#include <mma.h>
using namespace nvcuda;

#define NN 50000          // nodes per type
#define NE 1600000        // edges per edge type
#define CIN 11
#define HD 64
#define CAP 128           // max in-degree bucket (Poisson(32): P(>=128) ~ e^-81)
#define N16 (NN*16)
#define N64 (NN*64)

// ---------------- scratch (device globals; no allocation) ----------------
__device__ int            g_cnt[4][NN];       // per-edge-type in-degree
__device__ unsigned short g_col[4][NN*CAP];   // bucketed source ids (ushort)
__device__ __half g_x16[2][N16];        // fp16 x padded to 16-half rows
__device__ __half g_agg1[4][N16];       // layer-1 MEANS (fp16)
__device__ __half g_h1s16[N64], g_h1p16[N64];    // layer-1 activations (fp16)
__device__ __half g_agg2[4][N64];       // layer-2 MEANS (fp16)
__device__ __half g_wb1[2][48*64];      // fp16 layer-1 weights: 3 segs x 16 x 64
__device__ __half g_wb2[2][192*64];     // fp16 layer-2 weights: 3 segs x 64 x 64
__device__ float  g_b1[2][HD], g_b2[2][HD];   // bias pair sums

// ---------------- fused setup ----------------
#define R0 (4*NN)          // zero cnt
#define R1 (2*N16)         // xpad
#define R2 (2*48*64)       // wb1
#define R3 (2*192*64)      // wb2
#define R4 (2*2*HD)        // bias pairs
#define RTOT (R0+R1+R2+R3+R4)
__global__ void setup_kernel(const float* __restrict__ xs, const float* __restrict__ xp,
                             const float* __restrict__ w1l, const float* __restrict__ w1r,
                             const float* __restrict__ w2l, const float* __restrict__ w2r,
                             const float* __restrict__ b1l, const float* __restrict__ b2l) {
    int i = blockIdx.x*blockDim.x + threadIdx.x;
    if (i < R0) { ((int*)g_cnt)[i] = 0; return; }
    i -= R0;
    if (i < R1) {
        int half_ = i / N16;
        int j = i - half_*N16;
        int node = j >> 4, c = j & 15;
        const float* x = half_ ? xp : xs;
        ((__half*)g_x16)[i] = (c < CIN) ? __float2half_rn(x[node*CIN + c]) : __half(0.f);
        return;
    }
    i -= R1;
    if (i < R2) {
        int ty = i / 3072;
        int j = i - ty*3072;
        int r = j >> 6, c = j & 63;
        int seg = r >> 4, k = r & 15;
        float v = 0.f;
        if (k < CIN) {
            if (seg < 2) v = w1l[(seg*2 + ty)*CIN*HD + k*HD + c];
            else         v = w1r[ty*CIN*HD + k*HD + c] + w1r[(2+ty)*CIN*HD + k*HD + c];
        }
        g_wb1[ty][r*64 + c] = __float2half_rn(v);
        return;
    }
    i -= R2;
    if (i < R3) {
        int ty = i / 12288;
        int j = i - ty*12288;
        int r = j >> 6, c = j & 63;
        int seg = r >> 6, k = r & 63;
        float v;
        if (seg < 2) v = w2l[(seg*2 + ty)*HD*HD + k*HD + c];
        else         v = w2r[ty*HD*HD + k*HD + c] + w2r[(2+ty)*HD*HD + k*HD + c];
        g_wb2[ty][r*64 + c] = __float2half_rn(v);
        return;
    }
    i -= R3;
    if (i < R4) {
        int which = i >> 7;
        int ty = (i >> 6) & 1;
        int c = i & 63;
        if (which == 0) g_b1[ty][c] = b1l[ty*HD + c] + b1l[(2+ty)*HD + c];
        else            g_b2[ty][c] = b2l[ty*HD + c] + b2l[(2+ty)*HD + c];
    }
}

// ---------------- single-pass bucket placement (4 edges/thread) ------------
#define NE4 (NE/4)
#define EBLK4 ((NE4 + 255) / 256)
__global__ void place_all_kernel(const int* __restrict__ e0, const int* __restrict__ e1,
                                 const int* __restrict__ e2, const int* __restrict__ e3) {
    int t = blockIdx.x / EBLK4;
    int p = (blockIdx.x - t*EBLK4)*blockDim.x + threadIdx.x;
    if (p >= NE4) return;
    const int* ei = (t==0) ? e0 : (t==1) ? e1 : (t==2) ? e2 : e3;
    int4 s4 = *(const int4*)(ei + 4*p);
    int4 d4 = *(const int4*)(ei + NE + 4*p);
    int* cnt = g_cnt[t];
    unsigned short* col = g_col[t];
    int pos;
    pos = atomicAdd(&cnt[d4.x], 1); if (pos < CAP) col[(long)d4.x*CAP + pos] = (unsigned short)s4.x;
    pos = atomicAdd(&cnt[d4.y], 1); if (pos < CAP) col[(long)d4.y*CAP + pos] = (unsigned short)s4.y;
    pos = atomicAdd(&cnt[d4.z], 1); if (pos < CAP) col[(long)d4.z*CAP + pos] = (unsigned short)s4.z;
    pos = atomicAdd(&cnt[d4.w], 1); if (pos < CAP) col[(long)d4.w*CAP + pos] = (unsigned short)s4.w;
}

// ---------------- layer-1 gather (fp16 src/dst, 4 lanes/node, 8B each) -----
__global__ void gather1_kernel() {
    int gid = blockIdx.x*64 + (threadIdx.x >> 2);
    int lane = threadIdx.x & 3;
    if (gid >= 4*NN) return;
    int t = gid / NN, n = gid - t*NN;
    const __half* src = (t < 2) ? g_x16[0] : g_x16[1];
    int cnt = g_cnt[t][n];
    int deg = min(cnt, CAP);
    const unsigned short* col = g_col[t] + (long)n*CAP;
    float acc[4] = {0.f, 0.f, 0.f, 0.f};
    int e = 0;
    int nd4 = deg & ~3;
    ushort4 nxt;
    if (nd4 > 0) nxt = *(const ushort4*)col;
    for (; e < nd4; e += 4) {
        ushort4 s = nxt;
        if (e + 4 < nd4) nxt = *(const ushort4*)(col + e + 4);
        uint2 v0 = *(const uint2*)(src + (long)s.x*16 + lane*4);
        uint2 v1 = *(const uint2*)(src + (long)s.y*16 + lane*4);
        uint2 v2 = *(const uint2*)(src + (long)s.z*16 + lane*4);
        uint2 v3 = *(const uint2*)(src + (long)s.w*16 + lane*4);
        const __half2 *h0=(const __half2*)&v0, *h1=(const __half2*)&v1;
        const __half2 *h2=(const __half2*)&v2, *h3=(const __half2*)&v3;
#pragma unroll
        for (int j = 0; j < 2; j++) {
            float2 f0 = __half22float2(h0[j]);
            float2 f1 = __half22float2(h1[j]);
            float2 f2 = __half22float2(h2[j]);
            float2 f3 = __half22float2(h3[j]);
            acc[2*j]   += (f0.x + f1.x) + (f2.x + f3.x);
            acc[2*j+1] += (f0.y + f1.y) + (f2.y + f3.y);
        }
    }
    for (; e < deg; e++) {
        int s0 = col[e];
        uint2 v0 = *(const uint2*)(src + (long)s0*16 + lane*4);
        const __half2* h0 = (const __half2*)&v0;
#pragma unroll
        for (int j = 0; j < 2; j++) {
            float2 f0 = __half22float2(h0[j]);
            acc[2*j]   += f0.x;
            acc[2*j+1] += f0.y;
        }
    }
    float inv = 1.f / (float)max(cnt, 1);
    __half2 o[2];
    o[0] = __floats2half2_rn(acc[0]*inv, acc[1]*inv);
    o[1] = __floats2half2_rn(acc[2]*inv, acc[3]*inv);
    *(float2*)(g_agg1[t] + (long)n*16 + lane*4) = *(float2*)o;
}

// ---------------- layer-2 gather (fp16 src/dst, 8 lanes/node, 16B each) ----
__global__ void gather2_kernel() {
    int gid = blockIdx.x*32 + (threadIdx.x >> 3);
    int lane = threadIdx.x & 7;
    if (gid >= 4*NN) return;
    int t = gid / NN, n = gid - t*NN;
    const __half* src = (t < 2) ? g_h1s16 : g_h1p16;
    int cnt = g_cnt[t][n];
    int deg = min(cnt, CAP);
    const unsigned short* col = g_col[t] + (long)n*CAP;
    float acc[8] = {0,0,0,0,0,0,0,0};
    int e = 0;
    int nd4 = deg & ~3;
    ushort4 nxt;
    if (nd4 > 0) nxt = *(const ushort4*)col;
    for (; e < nd4; e += 4) {
        ushort4 s = nxt;
        if (e + 4 < nd4) nxt = *(const ushort4*)(col + e + 4);
        float4 r0 = *(const float4*)(src + (long)s.x*HD + lane*8);
        float4 r1 = *(const float4*)(src + (long)s.y*HD + lane*8);
        float4 r2 = *(const float4*)(src + (long)s.z*HD + lane*8);
        float4 r3 = *(const float4*)(src + (long)s.w*HD + lane*8);
        const __half2* h0 = (const __half2*)&r0;
        const __half2* h1 = (const __half2*)&r1;
        const __half2* h2 = (const __half2*)&r2;
        const __half2* h3 = (const __half2*)&r3;
#pragma unroll
        for (int j = 0; j < 4; j++) {
            float2 f0 = __half22float2(h0[j]);
            float2 f1 = __half22float2(h1[j]);
            float2 f2 = __half22float2(h2[j]);
            float2 f3 = __half22float2(h3[j]);
            acc[2*j]   += (f0.x + f1.x) + (f2.x + f3.x);
            acc[2*j+1] += (f0.y + f1.y) + (f2.y + f3.y);
        }
    }
    for (; e < deg; e++) {
        int s0 = col[e];
        float4 r0 = *(const float4*)(src + (long)s0*HD + lane*8);
        const __half2* h0 = (const __half2*)&r0;
#pragma unroll
        for (int j = 0; j < 4; j++) {
            float2 f0 = __half22float2(h0[j]);
            acc[2*j]   += f0.x;
            acc[2*j+1] += f0.y;
        }
    }
    float inv = 1.f / (float)max(cnt, 1);
    __half2 o[4];
#pragma unroll
    for (int j = 0; j < 4; j++)
        o[j] = __floats2half2_rn(acc[2*j]*inv, acc[2*j+1]*inv);
    *(float4*)(g_agg2[t] + (long)n*HD + lane*8) = *(float4*)o;
}

// ---------------- wmma GEMM: per-segment A staging, small smem -------------
struct GArgs {
    const __half *A0[2], *A1[2], *A2[2];
    const __half *B[2];
    const float  *bias[2];
    __half *C16[2];
    const float *wlin[2], *bfin[2];
    float *out[2];
    int lda;
    int final_;
};

#define ASTR 72
#define BSTR 72
#define CSTR 68
// smem: As (64*72 halves = 9216B) + Bs (9216B); Cs (64*68 floats = 17408B) aliased.
__global__ void gemm_wmma_kernel(GArgs g) {
    __shared__ char smem[64*ASTR*2 + 64*BSTR*2];   // 18432 B
    __half* As = (__half*)smem;
    __half* Bs = (__half*)(smem + 64*ASTR*2);
    float*  Cs = (float*)smem;

    const int tid = threadIdx.x;
    const int ty  = blockIdx.y;
    const int m0  = blockIdx.x*64;
    const int lda = g.lda;
    const __half* Aseg[3] = {g.A0[ty], g.A1[ty], g.A2[ty]};
    const __half* B = g.B[ty];

    wmma::fragment<wmma::matrix_a, 16,16,16, __half, wmma::row_major> af;
    wmma::fragment<wmma::matrix_b, 16,16,16, __half, wmma::row_major> bf0, bf1;
    wmma::fragment<wmma::accumulator, 16,16,16, float> c0, c1;
    wmma::fill_fragment(c0, 0.f);
    wmma::fill_fragment(c1, 0.f);

    const int warp = tid >> 5;
    const int wr = warp >> 1;      // 0..3 : 16-row group
    const int wc = warp & 1;       // 0..1 : 32-col group
    const int rowU = lda >> 3;     // float4 units per A row

    for (int seg = 0; seg < 3; seg++) {
        __syncthreads();
        // stage A segment (64 x lda)
        const __half* A = Aseg[seg];
        for (int u = tid; u < 64*rowU; u += 256) {
            int m = u / rowU;
            int h = (u - m*rowU) << 3;
            int gm = m0 + m;
            float4 v = make_float4(0.f,0.f,0.f,0.f);
            if (gm < NN) v = *(const float4*)(A + (long)gm*lda + h);
            *(float4*)(As + m*ASTR + h) = v;
        }
        // stage B segment (lda x 64)
        for (int u = tid; u < lda*8; u += 256) {
            int r = u >> 3, c = (u & 7) << 3;
            *(float4*)(Bs + r*BSTR + c) =
                *(const float4*)(B + (long)(seg*lda + r)*64 + c);
        }
        __syncthreads();
        for (int kc = 0; kc < (lda >> 4); kc++) {
            wmma::load_matrix_sync(af, As + (wr*16)*ASTR + kc*16, ASTR);
            wmma::load_matrix_sync(bf0, Bs + (kc*16)*BSTR + wc*32, BSTR);
            wmma::load_matrix_sync(bf1, Bs + (kc*16)*BSTR + wc*32 + 16, BSTR);
            wmma::mma_sync(c0, af, bf0, c0);
            wmma::mma_sync(c1, af, bf1, c1);
        }
    }

    __syncthreads();
    wmma::store_matrix_sync(Cs + (wr*16)*CSTR + wc*32, c0, CSTR, wmma::mem_row_major);
    wmma::store_matrix_sync(Cs + (wr*16)*CSTR + wc*32 + 16, c1, CSTR, wmma::mem_row_major);
    __syncthreads();

    const float* bias = g.bias[ty];
    int r = tid >> 2, lane = tid & 3;
    int gm = m0 + r;
    int cb = lane*16;
    if (g.final_) {
        const float* wl = g.wlin[ty];
        float s = 0.f;
#pragma unroll
        for (int c = 0; c < 16; c++) {
            float v = fmaxf(Cs[r*CSTR + cb + c] + bias[cb + c], 0.f);
            s = fmaf(v, wl[cb + c], s);
        }
        s += __shfl_xor_sync(0xffffffffu, s, 1, 4);
        s += __shfl_xor_sync(0xffffffffu, s, 2, 4);
        if (lane == 0 && gm < NN) g.out[ty][gm] = s + g.bfin[ty][0];
    } else if (gm < NN) {
        __half2 o[8];
#pragma unroll
        for (int j = 0; j < 8; j++) {
            float v0 = fmaxf(Cs[r*CSTR + cb + 2*j]   + bias[cb + 2*j],   0.f);
            float v1 = fmaxf(Cs[r*CSTR + cb + 2*j+1] + bias[cb + 2*j+1], 0.f);
            o[j] = __floats2half2_rn(v0, v1);
        }
        __half* dst = g.C16[ty] + (long)gm*HD + cb;
        *(float4*)dst       = *(float4*)&o[0];
        *(float4*)(dst + 8) = *(float4*)&o[4];
    }
}

// ---------------- launch ----------------
extern "C" void kernel_launch(void* const* d_in, const int* in_sizes, int n_in,
                              void* d_out, int out_size) {
    (void)in_sizes; (void)n_in; (void)out_size;
    const float* x_shop = (const float*)d_in[0];
    const float* x_pub  = (const float*)d_in[1];
    const float* w1_l   = (const float*)d_in[2];
    const float* b1_l   = (const float*)d_in[3];
    const float* w1_r   = (const float*)d_in[4];
    const float* w2_l   = (const float*)d_in[5];
    const float* b2_l   = (const float*)d_in[6];
    const float* w2_r   = (const float*)d_in[7];
    const float* wls    = (const float*)d_in[8];
    const float* bls    = (const float*)d_in[9];
    const float* wlp    = (const float*)d_in[10];
    const float* blp    = (const float*)d_in[11];
    const int* ei_ss    = (const int*)d_in[12];
    const int* ei_sp    = (const int*)d_in[13];
    const int* ei_ps    = (const int*)d_in[14];
    const int* ei_pp    = (const int*)d_in[15];

    __half *agg1, *agg2, *h1s16, *h1p16, *x16, *wb1, *wb2;
    float *b1, *b2;
    cudaGetSymbolAddress((void**)&agg1, g_agg1);
    cudaGetSymbolAddress((void**)&agg2, g_agg2);
    cudaGetSymbolAddress((void**)&h1s16, g_h1s16);
    cudaGetSymbolAddress((void**)&h1p16, g_h1p16);
    cudaGetSymbolAddress((void**)&x16,  g_x16);
    cudaGetSymbolAddress((void**)&wb1,  g_wb1);
    cudaGetSymbolAddress((void**)&wb2,  g_wb2);
    cudaGetSymbolAddress((void**)&b1,   g_b1);
    cudaGetSymbolAddress((void**)&b2,   g_b2);

    const int TB = 256;
    const int GB = (NN + 63) / 64;                // 782
    float* out = (float*)d_out;

    setup_kernel<<<(RTOT + TB - 1)/TB, TB>>>(x_shop, x_pub, w1_l, w1_r, w2_l, w2_r, b1_l, b2_l);
    place_all_kernel<<<4*EBLK4, TB>>>(ei_ss, ei_sp, ei_ps, ei_pp);

    // ---- layer 1 ----
    gather1_kernel<<<(4*NN + 63)/64, TB>>>();
    {
        GArgs a;
        a.A0[0] = agg1 + 0L*N16;  a.A0[1] = agg1 + 1L*N16;
        a.A1[0] = agg1 + 2L*N16;  a.A1[1] = agg1 + 3L*N16;
        a.A2[0] = x16 + 0L*N16;   a.A2[1] = x16 + 1L*N16;
        a.B[0] = wb1;             a.B[1] = wb1 + 48*64;
        a.bias[0] = b1;           a.bias[1] = b1 + HD;
        a.C16[0] = h1s16;         a.C16[1] = h1p16;
        a.wlin[0] = a.wlin[1] = nullptr;
        a.bfin[0] = a.bfin[1] = nullptr;
        a.out[0] = a.out[1] = nullptr;
        a.lda = 16; a.final_ = 0;
        gemm_wmma_kernel<<<dim3(GB,2), TB>>>(a);
    }

    // ---- layer 2 ----
    gather2_kernel<<<(4*NN + 31)/32, TB>>>();
    {
        GArgs a;
        a.A0[0] = agg2 + 0L*N64;  a.A0[1] = agg2 + 1L*N64;
        a.A1[0] = agg2 + 2L*N64;  a.A1[1] = agg2 + 3L*N64;
        a.A2[0] = h1s16;          a.A2[1] = h1p16;
        a.B[0] = wb2;             a.B[1] = wb2 + 192*64;
        a.bias[0] = b2;           a.bias[1] = b2 + HD;
        a.C16[0] = a.C16[1] = nullptr;
        a.wlin[0] = wls;          a.wlin[1] = wlp;
        a.bfin[0] = bls;          a.bfin[1] = blp;
        a.out[0] = out;           a.out[1] = out + NN;
        a.lda = 64; a.final_ = 1;
        gemm_wmma_kernel<<<dim3(GB,2), TB>>>(a);
    }
}

// round 10
// speedup vs baseline: 1.1288x; 1.0132x over previous
#include <cuda_runtime.h>
#include <cuda_fp16.h>
#include <mma.h>
using namespace nvcuda;

#define NN 50000          // nodes per type
#define NE 1600000        // edges per edge type
#define CIN 11
#define HD 64
#define CAP 128           // max in-degree bucket (Poisson(32): P(>=128) ~ e^-81)
#define N16 (NN*16)
#define N64 (NN*64)

// ---------------- scratch (device globals; no allocation) ----------------
__device__ int            g_cnt[4][NN];       // per-edge-type in-degree
__device__ unsigned short g_col[4][NN*CAP];   // bucketed source ids (ushort)
__device__ __half g_x16[2][N16];        // fp16 x padded to 16-half rows
__device__ __half g_agg1[4][N16];       // layer-1 MEANS (fp16)
__device__ __half g_h1s16[N64], g_h1p16[N64];    // layer-1 activations (fp16)
__device__ __half g_agg2[4][N64];       // layer-2 MEANS (fp16)
__device__ __half g_wb1[2][48*64];      // fp16 layer-1 weights: 3 segs x 16 x 64
__device__ __half g_wb2[2][192*64];     // fp16 layer-2 weights: 3 segs x 64 x 64
__device__ float  g_b1[2][HD], g_b2[2][HD];   // bias pair sums

// ---------------- zero counts (must precede placement) ----------------
__global__ void zero_cnt_kernel() {
    int i = blockIdx.x*blockDim.x + threadIdx.x;
    if (i < 4*NN) ((int*)g_cnt)[i] = 0;
}

// ---------------- fused placement + prep (independent block ranges) --------
#define NE4 (NE/4)
#define EBLK4 ((NE4 + 255) / 256)
#define PBLK (4*EBLK4)
// prep ranges
#define R1 (2*N16)         // xpad
#define R2 (2*48*64)       // wb1
#define R3 (2*192*64)      // wb2
#define R4 (2*2*HD)        // bias pairs
#define RTOT2 (R1+R2+R3+R4)
#define QBLK ((RTOT2 + 255)/256)

__global__ void prep_place_kernel(const float* __restrict__ xs, const float* __restrict__ xp,
                                  const float* __restrict__ w1l, const float* __restrict__ w1r,
                                  const float* __restrict__ w2l, const float* __restrict__ w2r,
                                  const float* __restrict__ b1l, const float* __restrict__ b2l,
                                  const int* __restrict__ e0, const int* __restrict__ e1,
                                  const int* __restrict__ e2, const int* __restrict__ e3) {
    if (blockIdx.x < PBLK) {
        // ---- edge placement (4 edges/thread) ----
        int t = blockIdx.x / EBLK4;
        int p = (blockIdx.x - t*EBLK4)*blockDim.x + threadIdx.x;
        if (p >= NE4) return;
        const int* ei = (t==0) ? e0 : (t==1) ? e1 : (t==2) ? e2 : e3;
        int4 s4 = *(const int4*)(ei + 4*p);
        int4 d4 = *(const int4*)(ei + NE + 4*p);
        int* cnt = g_cnt[t];
        unsigned short* col = g_col[t];
        int pos;
        pos = atomicAdd(&cnt[d4.x], 1); if (pos < CAP) col[(long)d4.x*CAP + pos] = (unsigned short)s4.x;
        pos = atomicAdd(&cnt[d4.y], 1); if (pos < CAP) col[(long)d4.y*CAP + pos] = (unsigned short)s4.y;
        pos = atomicAdd(&cnt[d4.z], 1); if (pos < CAP) col[(long)d4.z*CAP + pos] = (unsigned short)s4.z;
        pos = atomicAdd(&cnt[d4.w], 1); if (pos < CAP) col[(long)d4.w*CAP + pos] = (unsigned short)s4.w;
        return;
    }
    int i = (blockIdx.x - PBLK)*blockDim.x + threadIdx.x;
    if (i < R1) {
        int half_ = i / N16;
        int j = i - half_*N16;
        int node = j >> 4, c = j & 15;
        const float* x = half_ ? xp : xs;
        ((__half*)g_x16)[i] = (c < CIN) ? __float2half_rn(x[node*CIN + c]) : __half(0.f);
        return;
    }
    i -= R1;
    if (i < R2) {
        int ty = i / 3072;
        int j = i - ty*3072;
        int r = j >> 6, c = j & 63;
        int seg = r >> 4, k = r & 15;
        float v = 0.f;
        if (k < CIN) {
            if (seg < 2) v = w1l[(seg*2 + ty)*CIN*HD + k*HD + c];
            else         v = w1r[ty*CIN*HD + k*HD + c] + w1r[(2+ty)*CIN*HD + k*HD + c];
        }
        g_wb1[ty][r*64 + c] = __float2half_rn(v);
        return;
    }
    i -= R2;
    if (i < R3) {
        int ty = i / 12288;
        int j = i - ty*12288;
        int r = j >> 6, c = j & 63;
        int seg = r >> 6, k = r & 63;
        float v;
        if (seg < 2) v = w2l[(seg*2 + ty)*HD*HD + k*HD + c];
        else         v = w2r[ty*HD*HD + k*HD + c] + w2r[(2+ty)*HD*HD + k*HD + c];
        g_wb2[ty][r*64 + c] = __float2half_rn(v);
        return;
    }
    i -= R3;
    if (i < R4) {
        int which = i >> 7;
        int ty = (i >> 6) & 1;
        int c = i & 63;
        if (which == 0) g_b1[ty][c] = b1l[ty*HD + c] + b1l[(2+ty)*HD + c];
        else            g_b2[ty][c] = b2l[ty*HD + c] + b2l[(2+ty)*HD + c];
    }
}

// ---------------- layer-1 gather (fp16 src/dst, 4 lanes/node, 8B each) -----
__global__ void gather1_kernel() {
    int gid = blockIdx.x*64 + (threadIdx.x >> 2);
    int lane = threadIdx.x & 3;
    if (gid >= 4*NN) return;
    int t = gid / NN, n = gid - t*NN;
    const __half* src = (t < 2) ? g_x16[0] : g_x16[1];
    int cnt = g_cnt[t][n];
    int deg = min(cnt, CAP);
    const unsigned short* col = g_col[t] + (long)n*CAP;
    float acc[4] = {0.f, 0.f, 0.f, 0.f};
    int e = 0;
    int nd4 = deg & ~3;
    ushort4 nxt;
    if (nd4 > 0) nxt = *(const ushort4*)col;
    for (; e < nd4; e += 4) {
        ushort4 s = nxt;
        if (e + 4 < nd4) nxt = *(const ushort4*)(col + e + 4);
        uint2 v0 = *(const uint2*)(src + (long)s.x*16 + lane*4);
        uint2 v1 = *(const uint2*)(src + (long)s.y*16 + lane*4);
        uint2 v2 = *(const uint2*)(src + (long)s.z*16 + lane*4);
        uint2 v3 = *(const uint2*)(src + (long)s.w*16 + lane*4);
        const __half2 *h0=(const __half2*)&v0, *h1=(const __half2*)&v1;
        const __half2 *h2=(const __half2*)&v2, *h3=(const __half2*)&v3;
#pragma unroll
        for (int j = 0; j < 2; j++) {
            float2 f0 = __half22float2(h0[j]);
            float2 f1 = __half22float2(h1[j]);
            float2 f2 = __half22float2(h2[j]);
            float2 f3 = __half22float2(h3[j]);
            acc[2*j]   += (f0.x + f1.x) + (f2.x + f3.x);
            acc[2*j+1] += (f0.y + f1.y) + (f2.y + f3.y);
        }
    }
    for (; e < deg; e++) {
        int s0 = col[e];
        uint2 v0 = *(const uint2*)(src + (long)s0*16 + lane*4);
        const __half2* h0 = (const __half2*)&v0;
#pragma unroll
        for (int j = 0; j < 2; j++) {
            float2 f0 = __half22float2(h0[j]);
            acc[2*j]   += f0.x;
            acc[2*j+1] += f0.y;
        }
    }
    float inv = 1.f / (float)max(cnt, 1);
    __half2 o[2];
    o[0] = __floats2half2_rn(acc[0]*inv, acc[1]*inv);
    o[1] = __floats2half2_rn(acc[2]*inv, acc[3]*inv);
    *(float2*)(g_agg1[t] + (long)n*16 + lane*4) = *(float2*)o;
}

// ---------------- layer-2 gather (fp16 src/dst, 8 lanes/node, 16B each) ----
__global__ void gather2_kernel() {
    int gid = blockIdx.x*32 + (threadIdx.x >> 3);
    int lane = threadIdx.x & 7;
    if (gid >= 4*NN) return;
    int t = gid / NN, n = gid - t*NN;
    const __half* src = (t < 2) ? g_h1s16 : g_h1p16;
    int cnt = g_cnt[t][n];
    int deg = min(cnt, CAP);
    const unsigned short* col = g_col[t] + (long)n*CAP;
    float acc[8] = {0,0,0,0,0,0,0,0};
    int e = 0;
    int nd4 = deg & ~3;
    ushort4 nxt;
    if (nd4 > 0) nxt = *(const ushort4*)col;
    for (; e < nd4; e += 4) {
        ushort4 s = nxt;
        if (e + 4 < nd4) nxt = *(const ushort4*)(col + e + 4);
        float4 r0 = *(const float4*)(src + (long)s.x*HD + lane*8);
        float4 r1 = *(const float4*)(src + (long)s.y*HD + lane*8);
        float4 r2 = *(const float4*)(src + (long)s.z*HD + lane*8);
        float4 r3 = *(const float4*)(src + (long)s.w*HD + lane*8);
        const __half2* h0 = (const __half2*)&r0;
        const __half2* h1 = (const __half2*)&r1;
        const __half2* h2 = (const __half2*)&r2;
        const __half2* h3 = (const __half2*)&r3;
#pragma unroll
        for (int j = 0; j < 4; j++) {
            float2 f0 = __half22float2(h0[j]);
            float2 f1 = __half22float2(h1[j]);
            float2 f2 = __half22float2(h2[j]);
            float2 f3 = __half22float2(h3[j]);
            acc[2*j]   += (f0.x + f1.x) + (f2.x + f3.x);
            acc[2*j+1] += (f0.y + f1.y) + (f2.y + f3.y);
        }
    }
    for (; e < deg; e++) {
        int s0 = col[e];
        float4 r0 = *(const float4*)(src + (long)s0*HD + lane*8);
        const __half2* h0 = (const __half2*)&r0;
#pragma unroll
        for (int j = 0; j < 4; j++) {
            float2 f0 = __half22float2(h0[j]);
            acc[2*j]   += f0.x;
            acc[2*j+1] += f0.y;
        }
    }
    float inv = 1.f / (float)max(cnt, 1);
    __half2 o[4];
#pragma unroll
    for (int j = 0; j < 4; j++)
        o[j] = __floats2half2_rn(acc[2*j]*inv, acc[2*j+1]*inv);
    *(float4*)(g_agg2[t] + (long)n*HD + lane*8) = *(float4*)o;
}

// ---------------- layer-1 GEMM: single-pass K=48 concat ----------------
struct G1Args {
    const __half *A0[2], *A1[2], *A2[2];   // each 64xK16, lda 16
    const __half *B[2];                    // 48 x 64
    const float  *bias[2];
    __half *C16[2];
};

#define A1STR 56
#define B1STR 72
#define C1STR 68

__global__ void gemm1_kernel(G1Args g) {
    __shared__ char smem[64*C1STR*4];      // 17408 B (max of stage/epilogue)
    __half* As = (__half*)smem;            // 64 x 56 halves = 7168 B
    __half* Bs = (__half*)(smem + 64*A1STR*2);  // 48 x 72 halves = 6912 B
    float*  Cs = (float*)smem;

    const int tid = threadIdx.x;
    const int ty  = blockIdx.y;
    const int m0  = blockIdx.x*64;
    const __half* Aseg[3] = {g.A0[ty], g.A1[ty], g.A2[ty]};
    const __half* B = g.B[ty];

    // stage A: 64 rows x 48 halves (3 segs of 16)
    for (int u = tid; u < 64*6; u += 256) {
        int m = u / 6;
        int h = (u - m*6) << 3;
        int seg = h >> 4, off = h & 15;
        int gm = m0 + m;
        float4 v = make_float4(0.f,0.f,0.f,0.f);
        if (gm < NN) v = *(const float4*)(Aseg[seg] + (long)gm*16 + off);
        *(float4*)(As + m*A1STR + h) = v;
    }
    // stage B: 48 rows x 64
    for (int u = tid; u < 48*8; u += 256) {
        int r = u >> 3, c = (u & 7) << 3;
        *(float4*)(Bs + r*B1STR + c) = *(const float4*)(B + (long)r*64 + c);
    }
    __syncthreads();

    wmma::fragment<wmma::matrix_a, 16,16,16, __half, wmma::row_major> af;
    wmma::fragment<wmma::matrix_b, 16,16,16, __half, wmma::row_major> bf0, bf1;
    wmma::fragment<wmma::accumulator, 16,16,16, float> c0, c1;
    wmma::fill_fragment(c0, 0.f);
    wmma::fill_fragment(c1, 0.f);
    const int warp = tid >> 5;
    const int wr = warp >> 1, wc = warp & 1;
#pragma unroll
    for (int kc = 0; kc < 3; kc++) {
        wmma::load_matrix_sync(af, As + (wr*16)*A1STR + kc*16, A1STR);
        wmma::load_matrix_sync(bf0, Bs + (kc*16)*B1STR + wc*32, B1STR);
        wmma::load_matrix_sync(bf1, Bs + (kc*16)*B1STR + wc*32 + 16, B1STR);
        wmma::mma_sync(c0, af, bf0, c0);
        wmma::mma_sync(c1, af, bf1, c1);
    }
    __syncthreads();
    wmma::store_matrix_sync(Cs + (wr*16)*C1STR + wc*32, c0, C1STR, wmma::mem_row_major);
    wmma::store_matrix_sync(Cs + (wr*16)*C1STR + wc*32 + 16, c1, C1STR, wmma::mem_row_major);
    __syncthreads();

    const float* bias = g.bias[ty];
    int r = tid >> 2, lane = tid & 3;
    int gm = m0 + r;
    int cb = lane*16;
    if (gm < NN) {
        __half2 o[8];
#pragma unroll
        for (int j = 0; j < 8; j++) {
            float v0 = fmaxf(Cs[r*C1STR + cb + 2*j]   + bias[cb + 2*j],   0.f);
            float v1 = fmaxf(Cs[r*C1STR + cb + 2*j+1] + bias[cb + 2*j+1], 0.f);
            o[j] = __floats2half2_rn(v0, v1);
        }
        __half* dst = g.C16[ty] + (long)gm*HD + cb;
        *(float4*)dst       = *(float4*)&o[0];
        *(float4*)(dst + 8) = *(float4*)&o[4];
    }
}

// ---------------- layer-2 GEMM: 128-row tile + fused final linear ----------
struct G2Args {
    const __half *A0[2], *A1[2], *A2[2];   // each 50000 x 64
    const __half *B[2];                    // 192 x 64
    const float  *bias[2];
    const float  *wlin[2], *bfin[2];
    float *out[2];
};

#define A2STR 72
#define B2STR 72
#define C2STR 68

__global__ void gemm2_kernel(G2Args g) {
    __shared__ char smem[128*C2STR*4];     // 34816 B
    __half* As = (__half*)smem;            // 128 x 72 = 18432 B
    __half* Bs = (__half*)(smem + 128*A2STR*2);  // 64 x 72 = 9216 B
    float*  Cs = (float*)smem;

    const int tid = threadIdx.x;
    const int ty  = blockIdx.y;
    const int m0  = blockIdx.x*128;
    const __half* Aseg[3] = {g.A0[ty], g.A1[ty], g.A2[ty]};
    const __half* B = g.B[ty];

    wmma::fragment<wmma::matrix_a, 16,16,16, __half, wmma::row_major> af;
    wmma::fragment<wmma::matrix_b, 16,16,16, __half, wmma::row_major> bf;
    wmma::fragment<wmma::accumulator, 16,16,16, float> c[4];
#pragma unroll
    for (int j = 0; j < 4; j++) wmma::fill_fragment(c[j], 0.f);

    const int wr = tid >> 5;   // warp = 16-row group (0..7)

#pragma unroll 1
    for (int seg = 0; seg < 3; seg++) {
        __syncthreads();
        const __half* A = Aseg[seg];
        for (int u = tid; u < 128*8; u += 256) {
            int m = u >> 3;
            int h = (u & 7) << 3;
            int gm = m0 + m;
            float4 v = make_float4(0.f,0.f,0.f,0.f);
            if (gm < NN) v = *(const float4*)(A + (long)gm*HD + h);
            *(float4*)(As + m*A2STR + h) = v;
        }
        for (int u = tid; u < 64*8; u += 256) {
            int r = u >> 3, cc = (u & 7) << 3;
            *(float4*)(Bs + r*B2STR + cc) = *(const float4*)(B + (long)(seg*64 + r)*64 + cc);
        }
        __syncthreads();
#pragma unroll
        for (int kc = 0; kc < 4; kc++) {
            wmma::load_matrix_sync(af, As + (wr*16)*A2STR + kc*16, A2STR);
#pragma unroll
            for (int j = 0; j < 4; j++) {
                wmma::load_matrix_sync(bf, Bs + (kc*16)*B2STR + j*16, B2STR);
                wmma::mma_sync(c[j], af, bf, c[j]);
            }
        }
    }

    __syncthreads();
#pragma unroll
    for (int j = 0; j < 4; j++)
        wmma::store_matrix_sync(Cs + (wr*16)*C2STR + j*16, c[j], C2STR, wmma::mem_row_major);
    __syncthreads();

    // fused final: out[m] = relu(row + bias) . wlin + bfin
    const float* bias = g.bias[ty];
    const float* wl = g.wlin[ty];
    int r = tid >> 1, lane = tid & 1;
    int gm = m0 + r;
    int cb = lane*32;
    float s = 0.f;
#pragma unroll
    for (int cc = 0; cc < 32; cc++) {
        float v = fmaxf(Cs[r*C2STR + cb + cc] + bias[cb + cc], 0.f);
        s = fmaf(v, wl[cb + cc], s);
    }
    s += __shfl_xor_sync(0xffffffffu, s, 1, 2);
    if (lane == 0 && gm < NN) g.out[ty][gm] = s + g.bfin[ty][0];
}

// ---------------- launch ----------------
extern "C" void kernel_launch(void* const* d_in, const int* in_sizes, int n_in,
                              void* d_out, int out_size) {
    (void)in_sizes; (void)n_in; (void)out_size;
    const float* x_shop = (const float*)d_in[0];
    const float* x_pub  = (const float*)d_in[1];
    const float* w1_l   = (const float*)d_in[2];
    const float* b1_l   = (const float*)d_in[3];
    const float* w1_r   = (const float*)d_in[4];
    const float* w2_l   = (const float*)d_in[5];
    const float* b2_l   = (const float*)d_in[6];
    const float* w2_r   = (const float*)d_in[7];
    const float* wls    = (const float*)d_in[8];
    const float* bls    = (const float*)d_in[9];
    const float* wlp    = (const float*)d_in[10];
    const float* blp    = (const float*)d_in[11];
    const int* ei_ss    = (const int*)d_in[12];
    const int* ei_sp    = (const int*)d_in[13];
    const int* ei_ps    = (const int*)d_in[14];
    const int* ei_pp    = (const int*)d_in[15];

    __half *agg1, *agg2, *h1s16, *h1p16, *x16, *wb1, *wb2;
    float *b1, *b2;
    cudaGetSymbolAddress((void**)&agg1, g_agg1);
    cudaGetSymbolAddress((void**)&agg2, g_agg2);
    cudaGetSymbolAddress((void**)&h1s16, g_h1s16);
    cudaGetSymbolAddress((void**)&h1p16, g_h1p16);
    cudaGetSymbolAddress((void**)&x16,  g_x16);
    cudaGetSymbolAddress((void**)&wb1,  g_wb1);
    cudaGetSymbolAddress((void**)&wb2,  g_wb2);
    cudaGetSymbolAddress((void**)&b1,   g_b1);
    cudaGetSymbolAddress((void**)&b2,   g_b2);

    const int TB = 256;
    const int GB1 = (NN + 63) / 64;               // 782
    const int GB2 = (NN + 127) / 128;             // 391
    float* out = (float*)d_out;

    zero_cnt_kernel<<<(4*NN + TB - 1)/TB, TB>>>();
    prep_place_kernel<<<PBLK + QBLK, TB>>>(x_shop, x_pub, w1_l, w1_r, w2_l, w2_r,
                                           b1_l, b2_l, ei_ss, ei_sp, ei_ps, ei_pp);

    // ---- layer 1 ----
    gather1_kernel<<<(4*NN + 63)/64, TB>>>();
    {
        G1Args a;
        a.A0[0] = agg1 + 0L*N16;  a.A0[1] = agg1 + 1L*N16;
        a.A1[0] = agg1 + 2L*N16;  a.A1[1] = agg1 + 3L*N16;
        a.A2[0] = x16 + 0L*N16;   a.A2[1] = x16 + 1L*N16;
        a.B[0] = wb1;             a.B[1] = wb1 + 48*64;
        a.bias[0] = b1;           a.bias[1] = b1 + HD;
        a.C16[0] = h1s16;         a.C16[1] = h1p16;
        gemm1_kernel<<<dim3(GB1,2), TB>>>(a);
    }

    // ---- layer 2 ----
    gather2_kernel<<<(4*NN + 31)/32, TB>>>();
    {
        G2Args a;
        a.A0[0] = agg2 + 0L*N64;  a.A0[1] = agg2 + 1L*N64;
        a.A1[0] = agg2 + 2L*N64;  a.A1[1] = agg2 + 3L*N64;
        a.A2[0] = h1s16;          a.A2[1] = h1p16;
        a.B[0] = wb2;             a.B[1] = wb2 + 192*64;
        a.bias[0] = b2;           a.bias[1] = b2 + HD;
        a.wlin[0] = wls;          a.wlin[1] = wlp;
        a.bfin[0] = bls;          a.bfin[1] = blp;
        a.out[0] = out;           a.out[1] = out + NN;
        gemm2_kernel<<<dim3(GB2,2), TB>>>(a);
    }
}

// round 11
// speedup vs baseline: 1.1620x; 1.0294x over previous
#include <cuda_runtime.h>
#include <cuda_fp16.h>
#include <mma.h>
using namespace nvcuda;

#define NN 50000          // nodes per type
#define NE 1600000        // edges per edge type
#define CIN 11
#define HD 64
#define CAP 128           // max in-degree bucket (Poisson(32): P(>=128) ~ e^-81)
#define N16 (NN*16)
#define N64 (NN*64)

// ---------------- scratch (device globals; no allocation) ----------------
__device__ int            g_cnt[4][NN];       // per-edge-type in-degree
__device__ unsigned short g_col[4][NN*CAP];   // bucketed source ids (ushort)
__device__ __half g_x16[2][N16];        // fp16 x padded to 16-half rows
__device__ __half g_agg1[4][N16];       // layer-1 MEANS (fp16)
__device__ __half g_h1s16[N64], g_h1p16[N64];    // layer-1 activations (fp16)
__device__ __half g_agg2[4][N64];       // layer-2 MEANS (fp16)
__device__ __half g_wb1[2][48*64];      // fp16 layer-1 weights: 3 segs x 16 x 64
__device__ __half g_wb2[2][192*64];     // fp16 layer-2 weights: 3 segs x 64 x 64
__device__ float  g_b1[2][HD], g_b2[2][HD];   // bias pair sums

// ---------------- zero counts (must precede placement) ----------------
__global__ void zero_cnt_kernel() {
    int i = blockIdx.x*blockDim.x + threadIdx.x;
    if (i < 4*NN) ((int*)g_cnt)[i] = 0;
}

// ---------------- fused placement + prep (independent block ranges) --------
#define NE8 (NE/8)
#define EBLK8 ((NE8 + 255) / 256)
#define PBLK (4*EBLK8)
// prep ranges
#define R1 (2*N16)         // xpad
#define R2 (2*48*64)       // wb1
#define R3 (2*192*64)      // wb2
#define R4 (2*2*HD)        // bias pairs
#define RTOT2 (R1+R2+R3+R4)
#define QBLK ((RTOT2 + 255)/256)

__global__ void prep_place_kernel(const float* __restrict__ xs, const float* __restrict__ xp,
                                  const float* __restrict__ w1l, const float* __restrict__ w1r,
                                  const float* __restrict__ w2l, const float* __restrict__ w2r,
                                  const float* __restrict__ b1l, const float* __restrict__ b2l,
                                  const int* __restrict__ e0, const int* __restrict__ e1,
                                  const int* __restrict__ e2, const int* __restrict__ e3) {
    if (blockIdx.x < PBLK) {
        // ---- edge placement (8 edges/thread) ----
        int t = blockIdx.x / EBLK8;
        int p = (blockIdx.x - t*EBLK8)*blockDim.x + threadIdx.x;
        if (p >= NE8) return;
        const int* ei = (t==0) ? e0 : (t==1) ? e1 : (t==2) ? e2 : e3;
        int4 sa = *(const int4*)(ei + 8*p);
        int4 sb = *(const int4*)(ei + 8*p + 4);
        int4 da = *(const int4*)(ei + NE + 8*p);
        int4 db = *(const int4*)(ei + NE + 8*p + 4);
        int* cnt = g_cnt[t];
        unsigned short* col = g_col[t];
        int pos;
        pos = atomicAdd(&cnt[da.x], 1); if (pos < CAP) col[(long)da.x*CAP + pos] = (unsigned short)sa.x;
        pos = atomicAdd(&cnt[da.y], 1); if (pos < CAP) col[(long)da.y*CAP + pos] = (unsigned short)sa.y;
        pos = atomicAdd(&cnt[da.z], 1); if (pos < CAP) col[(long)da.z*CAP + pos] = (unsigned short)sa.z;
        pos = atomicAdd(&cnt[da.w], 1); if (pos < CAP) col[(long)da.w*CAP + pos] = (unsigned short)sa.w;
        pos = atomicAdd(&cnt[db.x], 1); if (pos < CAP) col[(long)db.x*CAP + pos] = (unsigned short)sb.x;
        pos = atomicAdd(&cnt[db.y], 1); if (pos < CAP) col[(long)db.y*CAP + pos] = (unsigned short)sb.y;
        pos = atomicAdd(&cnt[db.z], 1); if (pos < CAP) col[(long)db.z*CAP + pos] = (unsigned short)sb.z;
        pos = atomicAdd(&cnt[db.w], 1); if (pos < CAP) col[(long)db.w*CAP + pos] = (unsigned short)sb.w;
        return;
    }
    int i = (blockIdx.x - PBLK)*blockDim.x + threadIdx.x;
    if (i < R1) {
        int half_ = i / N16;
        int j = i - half_*N16;
        int node = j >> 4, c = j & 15;
        const float* x = half_ ? xp : xs;
        ((__half*)g_x16)[i] = (c < CIN) ? __float2half_rn(x[node*CIN + c]) : __half(0.f);
        return;
    }
    i -= R1;
    if (i < R2) {
        int ty = i / 3072;
        int j = i - ty*3072;
        int r = j >> 6, c = j & 63;
        int seg = r >> 4, k = r & 15;
        float v = 0.f;
        if (k < CIN) {
            if (seg < 2) v = w1l[(seg*2 + ty)*CIN*HD + k*HD + c];
            else         v = w1r[ty*CIN*HD + k*HD + c] + w1r[(2+ty)*CIN*HD + k*HD + c];
        }
        g_wb1[ty][r*64 + c] = __float2half_rn(v);
        return;
    }
    i -= R2;
    if (i < R3) {
        int ty = i / 12288;
        int j = i - ty*12288;
        int r = j >> 6, c = j & 63;
        int seg = r >> 6, k = r & 63;
        float v;
        if (seg < 2) v = w2l[(seg*2 + ty)*HD*HD + k*HD + c];
        else         v = w2r[ty*HD*HD + k*HD + c] + w2r[(2+ty)*HD*HD + k*HD + c];
        g_wb2[ty][r*64 + c] = __float2half_rn(v);
        return;
    }
    i -= R3;
    if (i < R4) {
        int which = i >> 7;
        int ty = (i >> 6) & 1;
        int c = i & 63;
        if (which == 0) g_b1[ty][c] = b1l[ty*HD + c] + b1l[(2+ty)*HD + c];
        else            g_b2[ty][c] = b2l[ty*HD + c] + b2l[(2+ty)*HD + c];
    }
}

// ---------------- layer-1 gather (fp16, 4 lanes/node, 8B, unroll 8) --------
__global__ void gather1_kernel() {
    int gid = blockIdx.x*64 + (threadIdx.x >> 2);
    int lane = threadIdx.x & 3;
    if (gid >= 4*NN) return;
    int t = gid / NN, n = gid - t*NN;
    const __half* src = (t < 2) ? g_x16[0] : g_x16[1];
    int cnt = g_cnt[t][n];
    int deg = min(cnt, CAP);
    const unsigned short* col = g_col[t] + (long)n*CAP;
    float acc[4] = {0.f, 0.f, 0.f, 0.f};
    int e = 0;
    int nd8 = deg & ~7;
    for (; e < nd8; e += 8) {
        uint4 cw = *(const uint4*)(col + e);
        int s[8];
        s[0] = cw.x & 0xffff; s[1] = cw.x >> 16;
        s[2] = cw.y & 0xffff; s[3] = cw.y >> 16;
        s[4] = cw.z & 0xffff; s[5] = cw.z >> 16;
        s[6] = cw.w & 0xffff; s[7] = cw.w >> 16;
        uint2 v[8];
#pragma unroll
        for (int q = 0; q < 8; q++)
            v[q] = *(const uint2*)(src + (long)s[q]*16 + lane*4);
#pragma unroll
        for (int q = 0; q < 8; q++) {
            const __half2* h = (const __half2*)&v[q];
#pragma unroll
            for (int j = 0; j < 2; j++) {
                float2 f = __half22float2(h[j]);
                acc[2*j]   += f.x;
                acc[2*j+1] += f.y;
            }
        }
    }
    for (; e < deg; e++) {
        int s0 = col[e];
        uint2 v0 = *(const uint2*)(src + (long)s0*16 + lane*4);
        const __half2* h0 = (const __half2*)&v0;
#pragma unroll
        for (int j = 0; j < 2; j++) {
            float2 f0 = __half22float2(h0[j]);
            acc[2*j]   += f0.x;
            acc[2*j+1] += f0.y;
        }
    }
    float inv = 1.f / (float)max(cnt, 1);
    __half2 o[2];
    o[0] = __floats2half2_rn(acc[0]*inv, acc[1]*inv);
    o[1] = __floats2half2_rn(acc[2]*inv, acc[3]*inv);
    *(float2*)(g_agg1[t] + (long)n*16 + lane*4) = *(float2*)o;
}

// ---------------- layer-2 gather (fp16, 8 lanes/node, 16B, unroll 8) -------
__global__ void gather2_kernel() {
    int gid = blockIdx.x*32 + (threadIdx.x >> 3);
    int lane = threadIdx.x & 7;
    if (gid >= 4*NN) return;
    int t = gid / NN, n = gid - t*NN;
    const __half* src = (t < 2) ? g_h1s16 : g_h1p16;
    int cnt = g_cnt[t][n];
    int deg = min(cnt, CAP);
    const unsigned short* col = g_col[t] + (long)n*CAP;
    float acc[8] = {0,0,0,0,0,0,0,0};
    int e = 0;
    int nd8 = deg & ~7;
    for (; e < nd8; e += 8) {
        uint4 cw = *(const uint4*)(col + e);
        int s[8];
        s[0] = cw.x & 0xffff; s[1] = cw.x >> 16;
        s[2] = cw.y & 0xffff; s[3] = cw.y >> 16;
        s[4] = cw.z & 0xffff; s[5] = cw.z >> 16;
        s[6] = cw.w & 0xffff; s[7] = cw.w >> 16;
        float4 v[8];
#pragma unroll
        for (int q = 0; q < 8; q++)
            v[q] = *(const float4*)(src + (long)s[q]*HD + lane*8);
#pragma unroll
        for (int q = 0; q < 8; q++) {
            const __half2* h = (const __half2*)&v[q];
#pragma unroll
            for (int j = 0; j < 4; j++) {
                float2 f = __half22float2(h[j]);
                acc[2*j]   += f.x;
                acc[2*j+1] += f.y;
            }
        }
    }
    for (; e < deg; e++) {
        int s0 = col[e];
        float4 r0 = *(const float4*)(src + (long)s0*HD + lane*8);
        const __half2* h0 = (const __half2*)&r0;
#pragma unroll
        for (int j = 0; j < 4; j++) {
            float2 f0 = __half22float2(h0[j]);
            acc[2*j]   += f0.x;
            acc[2*j+1] += f0.y;
        }
    }
    float inv = 1.f / (float)max(cnt, 1);
    __half2 o[4];
#pragma unroll
    for (int j = 0; j < 4; j++)
        o[j] = __floats2half2_rn(acc[2*j]*inv, acc[2*j+1]*inv);
    *(float4*)(g_agg2[t] + (long)n*HD + lane*8) = *(float4*)o;
}

// ---------------- layer-1 GEMM: 128-row tile, single-pass K=48 -------------
struct G1Args {
    const __half *A0[2], *A1[2], *A2[2];   // each 50000 x 16 halves
    const __half *B[2];                    // 48 x 64
    const float  *bias[2];
    __half *C16[2];
};

#define A1STR 56
#define B1STR 72
#define C1STR 68

__global__ void gemm1_kernel(G1Args g) {
    __shared__ char smem[128*C1STR*4];     // 34816 B (epilogue dominates)
    __half* As = (__half*)smem;            // 128 x 56 halves = 14336 B
    __half* Bs = (__half*)(smem + 128*A1STR*2);  // 48 x 72 halves = 6912 B
    float*  Cs = (float*)smem;

    const int tid = threadIdx.x;
    const int ty  = blockIdx.y;
    const int m0  = blockIdx.x*128;
    const __half* Aseg[3] = {g.A0[ty], g.A1[ty], g.A2[ty]};
    const __half* B = g.B[ty];

    // stage A: 128 rows x 48 halves (3 segs of 16)
    for (int u = tid; u < 128*6; u += 256) {
        int m = u / 6;
        int h = (u - m*6) << 3;
        int seg = h >> 4, off = h & 15;
        int gm = m0 + m;
        float4 v = make_float4(0.f,0.f,0.f,0.f);
        if (gm < NN) v = *(const float4*)(Aseg[seg] + (long)gm*16 + off);
        *(float4*)(As + m*A1STR + h) = v;
    }
    // stage B: 48 rows x 64
    for (int u = tid; u < 48*8; u += 256) {
        int r = u >> 3, c = (u & 7) << 3;
        *(float4*)(Bs + r*B1STR + c) = *(const float4*)(B + (long)r*64 + c);
    }
    __syncthreads();

    wmma::fragment<wmma::matrix_a, 16,16,16, __half, wmma::row_major> af;
    wmma::fragment<wmma::matrix_b, 16,16,16, __half, wmma::row_major> bf;
    wmma::fragment<wmma::accumulator, 16,16,16, float> c[4];
#pragma unroll
    for (int j = 0; j < 4; j++) wmma::fill_fragment(c[j], 0.f);
    const int wr = tid >> 5;   // warp = 16-row group (0..7)
#pragma unroll
    for (int kc = 0; kc < 3; kc++) {
        wmma::load_matrix_sync(af, As + (wr*16)*A1STR + kc*16, A1STR);
#pragma unroll
        for (int j = 0; j < 4; j++) {
            wmma::load_matrix_sync(bf, Bs + (kc*16)*B1STR + j*16, B1STR);
            wmma::mma_sync(c[j], af, bf, c[j]);
        }
    }
    __syncthreads();
#pragma unroll
    for (int j = 0; j < 4; j++)
        wmma::store_matrix_sync(Cs + (wr*16)*C1STR + j*16, c[j], C1STR, wmma::mem_row_major);
    __syncthreads();

    const float* bias = g.bias[ty];
    int r = tid >> 1, lane = tid & 1;
    int gm = m0 + r;
    int cb = lane*32;
    if (gm < NN) {
        __half2 o[16];
#pragma unroll
        for (int j = 0; j < 16; j++) {
            float v0 = fmaxf(Cs[r*C1STR + cb + 2*j]   + bias[cb + 2*j],   0.f);
            float v1 = fmaxf(Cs[r*C1STR + cb + 2*j+1] + bias[cb + 2*j+1], 0.f);
            o[j] = __floats2half2_rn(v0, v1);
        }
        __half* dst = g.C16[ty] + (long)gm*HD + cb;
        *(float4*)dst        = *(float4*)&o[0];
        *(float4*)(dst + 8)  = *(float4*)&o[4];
        *(float4*)(dst + 16) = *(float4*)&o[8];
        *(float4*)(dst + 24) = *(float4*)&o[12];
    }
}

// ---------------- layer-2 GEMM: 128-row tile + fused final linear ----------
struct G2Args {
    const __half *A0[2], *A1[2], *A2[2];   // each 50000 x 64
    const __half *B[2];                    // 192 x 64
    const float  *bias[2];
    const float  *wlin[2], *bfin[2];
    float *out[2];
};

#define A2STR 72
#define B2STR 72
#define C2STR 68

__global__ void gemm2_kernel(G2Args g) {
    __shared__ char smem[128*C2STR*4];     // 34816 B
    __half* As = (__half*)smem;            // 128 x 72 = 18432 B
    __half* Bs = (__half*)(smem + 128*A2STR*2);  // 64 x 72 = 9216 B
    float*  Cs = (float*)smem;

    const int tid = threadIdx.x;
    const int ty  = blockIdx.y;
    const int m0  = blockIdx.x*128;
    const __half* Aseg[3] = {g.A0[ty], g.A1[ty], g.A2[ty]};
    const __half* B = g.B[ty];

    wmma::fragment<wmma::matrix_a, 16,16,16, __half, wmma::row_major> af;
    wmma::fragment<wmma::matrix_b, 16,16,16, __half, wmma::row_major> bf;
    wmma::fragment<wmma::accumulator, 16,16,16, float> c[4];
#pragma unroll
    for (int j = 0; j < 4; j++) wmma::fill_fragment(c[j], 0.f);

    const int wr = tid >> 5;   // warp = 16-row group (0..7)

#pragma unroll 1
    for (int seg = 0; seg < 3; seg++) {
        __syncthreads();
        const __half* A = Aseg[seg];
        for (int u = tid; u < 128*8; u += 256) {
            int m = u >> 3;
            int h = (u & 7) << 3;
            int gm = m0 + m;
            float4 v = make_float4(0.f,0.f,0.f,0.f);
            if (gm < NN) v = *(const float4*)(A + (long)gm*HD + h);
            *(float4*)(As + m*A2STR + h) = v;
        }
        for (int u = tid; u < 64*8; u += 256) {
            int r = u >> 3, cc = (u & 7) << 3;
            *(float4*)(Bs + r*B2STR + cc) = *(const float4*)(B + (long)(seg*64 + r)*64 + cc);
        }
        __syncthreads();
#pragma unroll
        for (int kc = 0; kc < 4; kc++) {
            wmma::load_matrix_sync(af, As + (wr*16)*A2STR + kc*16, A2STR);
#pragma unroll
            for (int j = 0; j < 4; j++) {
                wmma::load_matrix_sync(bf, Bs + (kc*16)*B2STR + j*16, B2STR);
                wmma::mma_sync(c[j], af, bf, c[j]);
            }
        }
    }

    __syncthreads();
#pragma unroll
    for (int j = 0; j < 4; j++)
        wmma::store_matrix_sync(Cs + (wr*16)*C2STR + j*16, c[j], C2STR, wmma::mem_row_major);
    __syncthreads();

    // fused final: out[m] = relu(row + bias) . wlin + bfin
    const float* bias = g.bias[ty];
    const float* wl = g.wlin[ty];
    int r = tid >> 1, lane = tid & 1;
    int gm = m0 + r;
    int cb = lane*32;
    float s = 0.f;
#pragma unroll
    for (int cc = 0; cc < 32; cc++) {
        float v = fmaxf(Cs[r*C2STR + cb + cc] + bias[cb + cc], 0.f);
        s = fmaf(v, wl[cb + cc], s);
    }
    s += __shfl_xor_sync(0xffffffffu, s, 1, 2);
    if (lane == 0 && gm < NN) g.out[ty][gm] = s + g.bfin[ty][0];
}

// ---------------- launch ----------------
extern "C" void kernel_launch(void* const* d_in, const int* in_sizes, int n_in,
                              void* d_out, int out_size) {
    (void)in_sizes; (void)n_in; (void)out_size;
    const float* x_shop = (const float*)d_in[0];
    const float* x_pub  = (const float*)d_in[1];
    const float* w1_l   = (const float*)d_in[2];
    const float* b1_l   = (const float*)d_in[3];
    const float* w1_r   = (const float*)d_in[4];
    const float* w2_l   = (const float*)d_in[5];
    const float* b2_l   = (const float*)d_in[6];
    const float* w2_r   = (const float*)d_in[7];
    const float* wls    = (const float*)d_in[8];
    const float* bls    = (const float*)d_in[9];
    const float* wlp    = (const float*)d_in[10];
    const float* blp    = (const float*)d_in[11];
    const int* ei_ss    = (const int*)d_in[12];
    const int* ei_sp    = (const int*)d_in[13];
    const int* ei_ps    = (const int*)d_in[14];
    const int* ei_pp    = (const int*)d_in[15];

    __half *agg1, *agg2, *h1s16, *h1p16, *x16, *wb1, *wb2;
    float *b1, *b2;
    cudaGetSymbolAddress((void**)&agg1, g_agg1);
    cudaGetSymbolAddress((void**)&agg2, g_agg2);
    cudaGetSymbolAddress((void**)&h1s16, g_h1s16);
    cudaGetSymbolAddress((void**)&h1p16, g_h1p16);
    cudaGetSymbolAddress((void**)&x16,  g_x16);
    cudaGetSymbolAddress((void**)&wb1,  g_wb1);
    cudaGetSymbolAddress((void**)&wb2,  g_wb2);
    cudaGetSymbolAddress((void**)&b1,   g_b1);
    cudaGetSymbolAddress((void**)&b2,   g_b2);

    const int TB = 256;
    const int GB2 = (NN + 127) / 128;             // 391
    float* out = (float*)d_out;

    zero_cnt_kernel<<<(4*NN + TB - 1)/TB, TB>>>();
    prep_place_kernel<<<PBLK + QBLK, TB>>>(x_shop, x_pub, w1_l, w1_r, w2_l, w2_r,
                                           b1_l, b2_l, ei_ss, ei_sp, ei_ps, ei_pp);

    // ---- layer 1 ----
    gather1_kernel<<<(4*NN + 63)/64, TB>>>();
    {
        G1Args a;
        a.A0[0] = agg1 + 0L*N16;  a.A0[1] = agg1 + 1L*N16;
        a.A1[0] = agg1 + 2L*N16;  a.A1[1] = agg1 + 3L*N16;
        a.A2[0] = x16 + 0L*N16;   a.A2[1] = x16 + 1L*N16;
        a.B[0] = wb1;             a.B[1] = wb1 + 48*64;
        a.bias[0] = b1;           a.bias[1] = b1 + HD;
        a.C16[0] = h1s16;         a.C16[1] = h1p16;
        gemm1_kernel<<<dim3(GB2,2), TB>>>(a);
    }

    // ---- layer 2 ----
    gather2_kernel<<<(4*NN + 31)/32, TB>>>();
    {
        G2Args a;
        a.A0[0] = agg2 + 0L*N64;  a.A0[1] = agg2 + 1L*N64;
        a.A1[0] = agg2 + 2L*N64;  a.A1[1] = agg2 + 3L*N64;
        a.A2[0] = h1s16;          a.A2[1] = h1p16;
        a.B[0] = wb2;             a.B[1] = wb2 + 192*64;
        a.bias[0] = b2;           a.bias[1] = b2 + HD;
        a.wlin[0] = wls;          a.wlin[1] = wlp;
        a.bfin[0] = bls;          a.bfin[1] = blp;
        a.out[0] = out;           a.out[1] = out + NN;
        gemm2_kernel<<<dim3(GB2,2), TB>>>(a);
    }
}